// round 7
// baseline (speedup 1.0000x reference)
#include <cuda_runtime.h>
#include <cuda_fp16.h>
#include <mma.h>
#include <stdint.h>

using namespace nvcuda;

#define N_NODES_MAX 100000
#define E_MAX       1600000
#define CH          128

// ---------------- scratch (static device globals; zero-initialized) ----------
__device__ __align__(16) int     g_cnt[N_NODES_MAX];   // MUST be zero at start of each run
__device__ __align__(16) int     g_rowstart[N_NODES_MAX];
__device__ __align__(16) int     g_cursor[N_NODES_MAX];
__device__ __align__(16) int     g_csr_src[E_MAX];
__device__ __align__(16) float   g_dinv[N_NODES_MAX];
__device__                int     g_total;              // zeroed in k_prep_count
__device__ __align__(16) __half2 g_xh[(size_t)N_NODES_MAX * 64];  // x in fp16
__device__ __align__(16) __half2 g_Wh[CH * CH / 2];               // W in fp16

// ---------------- kernel 1: convert x,W to fp16 + count in-degree -------------
// relies on g_cnt == 0 (zero-initialized .bss on run 1; re-zeroed by the final
// kernel of every run, so graph replays see the same state).
__global__ void k_prep_count(const float2* __restrict__ x2,
                             const float2* __restrict__ W2,
                             const int* __restrict__ ei, int E, int n) {
    int i = blockIdx.x * blockDim.x + threadIdx.x;
    int conv = n * 64;
    if (i < conv) g_xh[i] = __float22half2_rn(x2[i]);
    if (i < CH * CH / 2) g_Wh[i] = __float22half2_rn(W2[i]);
    if (i < E) {
        unsigned dst = (unsigned)ei[E + i];
        if (dst < (unsigned)n) atomicAdd(&g_cnt[dst], 1);
    }
    if (i == 0) g_total = 0;
}

// ---------------- kernel 2: allocate CSR ranges (no scan needed) --------------
// Row ranges need only be disjoint+contiguous, not ordered: warp-aggregated
// atomicAdd on one global cursor.
__global__ void k_alloc(int n) {
    int i    = blockIdx.x * blockDim.x + threadIdx.x;
    int lane = threadIdx.x & 31;
    int c = (i < n) ? g_cnt[i] : 0;

    // warp inclusive scan of c
    int pre = c;
    #pragma unroll
    for (int off = 1; off < 32; off <<= 1) {
        int t = __shfl_up_sync(0xffffffffu, pre, off);
        if (lane >= off) pre += t;
    }
    int base = 0;
    if (lane == 31) base = atomicAdd(&g_total, pre);
    base = __shfl_sync(0xffffffffu, base, 31);
    if (i < n) {
        int rs = base + pre - c;           // exclusive within warp
        g_rowstart[i] = rs;
        g_cursor[i]   = rs;
        g_dinv[i]     = rsqrtf(1.0f + (float)c);   // +1 self loop
    }
}

// ---------------- kernel 3: CSR fill ------------------------------------------
// afterwards g_cursor[d] == rowstart[d] + deg[d] (row end)
__global__ void k_fill(const int* __restrict__ ei, int E, int n) {
    int e = blockIdx.x * blockDim.x + threadIdx.x;
    if (e < E) {
        unsigned src = (unsigned)ei[e];
        unsigned dst = (unsigned)ei[E + e];
        if (src < (unsigned)n && dst < (unsigned)n) {
            int pos = atomicAdd(&g_cursor[dst], 1);
            if ((unsigned)pos < (unsigned)E_MAX)
                g_csr_src[pos] = (int)src;
        }
    }
}

// ---------------- kernel 4: fused aggregate + HMMA GEMM ------------------------
// Phase 1: each warp aggregates 16 nodes straight into the smem A tile (fp16).
// Phase 2: block GEMM  out[row0:row0+128] = A @ W + bias  (fp32 accum).
// Also re-zeroes g_cnt for the next graph replay.
__global__ void __launch_bounds__(256, 2)
k_agg_gemm(const float* __restrict__ bias, float* __restrict__ C, int M) {
    __shared__ __align__(16) __half As[128 * 136];   // padded ld = 136 halfs
    __shared__ float Es[8 * 256];

    const int tid  = threadIdx.x;
    const int wid  = tid >> 5;
    const int lane = tid & 31;
    const int row0 = blockIdx.x * 128;

    // ---- phase 1: aggregate ----
    for (int t = 0; t < 16; t++) {
        int r    = wid * 16 + t;          // 0..127 within tile
        int node = row0 + r;
        float4 acc = make_float4(0.f, 0.f, 0.f, 0.f);
        if (node < M) {
            float di = g_dinv[node];
            uint2 sv = ((const uint2*)(g_xh + (size_t)node * 64))[lane];
            float2 f0 = __half22float2(*(__half2*)&sv.x);
            float2 f1 = __half22float2(*(__half2*)&sv.y);
            float ws = di * di;
            acc = make_float4(f0.x * ws, f0.y * ws, f1.x * ws, f1.y * ws);

            int start = g_rowstart[node];
            int end   = g_cursor[node];      // == rowstart + deg after fill

            for (int p0 = start; p0 < end; p0 += 32) {
                int myp = p0 + lane;
                int s = 0; float w = 0.0f;
                if (myp < end) {
                    s = g_csr_src[myp];
                    w = di * g_dinv[s];
                }
                int cnt = min(32, end - p0);
                for (int j = 0; j < cnt; j++) {
                    int   sj = __shfl_sync(0xffffffffu, s, j);
                    float wj = __shfl_sync(0xffffffffu, w, j);
                    uint2 v  = ((const uint2*)(g_xh + (size_t)sj * 64))[lane];
                    float2 a = __half22float2(*(__half2*)&v.x);
                    float2 b = __half22float2(*(__half2*)&v.y);
                    acc.x += wj * a.x; acc.y += wj * a.y;
                    acc.z += wj * b.x; acc.w += wj * b.y;
                }
            }
        }
        __half2 o0 = __floats2half2_rn(acc.x, acc.y);
        __half2 o1 = __floats2half2_rn(acc.z, acc.w);
        uint2 ov = make_uint2(*(unsigned*)&o0, *(unsigned*)&o1);
        *(uint2*)(As + r * 136 + lane * 4) = ov;
    }
    __syncthreads();

    // ---- phase 2: HMMA GEMM ----
    const int warp_m = wid & 1;        // 0..1 (64 rows)
    const int warp_n = wid >> 1;       // 0..3 (32 cols)

    wmma::fragment<wmma::accumulator, 16, 16, 16, float> acc[4][2];
    #pragma unroll
    for (int mf = 0; mf < 4; mf++)
        #pragma unroll
        for (int nf = 0; nf < 2; nf++)
            wmma::fill_fragment(acc[mf][nf], 0.0f);

    const __half* Wh = (const __half*)g_Wh;

    #pragma unroll
    for (int k0 = 0; k0 < 128; k0 += 16) {
        wmma::fragment<wmma::matrix_a, 16, 16, 16, __half, wmma::row_major> af[4];
        #pragma unroll
        for (int mf = 0; mf < 4; mf++)
            wmma::load_matrix_sync(af[mf],
                As + (warp_m * 64 + mf * 16) * 136 + k0, 136);
        #pragma unroll
        for (int nf = 0; nf < 2; nf++) {
            wmma::fragment<wmma::matrix_b, 16, 16, 16, __half, wmma::row_major> bf;
            wmma::load_matrix_sync(bf, Wh + k0 * CH + warp_n * 32 + nf * 16, CH);
            #pragma unroll
            for (int mf = 0; mf < 4; mf++)
                wmma::mma_sync(acc[mf][nf], af[mf], bf, acc[mf][nf]);
        }
    }

    // epilogue: bounce frags through smem, add bias, coalesced fp32 store
    float* es = Es + wid * 256;
    #pragma unroll
    for (int mf = 0; mf < 4; mf++) {
        #pragma unroll
        for (int nf = 0; nf < 2; nf++) {
            wmma::store_matrix_sync(es, acc[mf][nf], 16, wmma::mem_row_major);
            __syncwarp();
            int r_in = lane >> 1;
            int c0   = (lane & 1) * 8;
            int gr   = row0 + warp_m * 64 + mf * 16 + r_in;
            int gc   = warp_n * 32 + nf * 16 + c0;
            if (gr < M) {
                float4 b0 = *(const float4*)(bias + gc);
                float4 b1 = *(const float4*)(bias + gc + 4);
                const float* p = es + r_in * 16 + c0;
                float4 o0 = make_float4(p[0] + b0.x, p[1] + b0.y,
                                        p[2] + b0.z, p[3] + b0.w);
                float4 o1 = make_float4(p[4] + b1.x, p[5] + b1.y,
                                        p[6] + b1.z, p[7] + b1.w);
                *(float4*)(C + (size_t)gr * CH + gc)     = o0;
                *(float4*)(C + (size_t)gr * CH + gc + 4) = o1;
            }
            __syncwarp();
        }
    }

    // restore invariant: g_cnt == 0 for next replay
    int gz = blockIdx.x * 256 + tid;
    if (gz < M) g_cnt[gz] = 0;
}

// ---------------- launch --------------------------------------------------------
extern "C" void kernel_launch(void* const* d_in, const int* in_sizes, int n_in,
                              void* d_out, int out_size) {
    const float* x    = (const float*)d_in[0];
    const int*   ei   = (const int*)d_in[1];     // int32 [2, E]
    const float* W    = (const float*)d_in[2];
    const float* bias = (const float*)d_in[3];
    float*       out  = (float*)d_out;

    int N = in_sizes[0] / CH;   // 100000
    int E = in_sizes[1] / 2;    // 1600000

    int prep_threads = N * 64;  // covers conversions and E
    if (prep_threads < E) prep_threads = E;

    k_prep_count<<<(prep_threads + 255) / 256, 256>>>((const float2*)x,
                                                      (const float2*)W, ei, E, N);
    k_alloc     <<<(N + 255) / 256, 256>>>(N);
    k_fill      <<<(E + 255) / 256, 256>>>(ei, E, N);
    k_agg_gemm  <<<(N + 127) / 128, 256>>>(bias, out, N);
}

// round 8
// speedup vs baseline: 1.3650x; 1.3650x over previous
#include <cuda_runtime.h>
#include <cuda_fp16.h>
#include <mma.h>
#include <stdint.h>

using namespace nvcuda;

#define N_NODES_MAX 100000
#define N_PAD       100096            // multiple of 128
#define E_MAX       1600000
#define CH          128

// ---------------- scratch (static device globals; zero-initialized) ----------
__device__ __align__(16) int     g_cnt[N_NODES_MAX];   // zero at start of each run
__device__ __align__(16) int     g_rowstart[N_NODES_MAX];
__device__ __align__(16) int     g_cursor[N_NODES_MAX];
__device__ __align__(16) int     g_csr_src[E_MAX];
__device__ __align__(16) float   g_dinv[N_NODES_MAX];
__device__               int     g_total;
__device__ __align__(16) __half2 g_xh[(size_t)N_NODES_MAX * 64];  // x in fp16
__device__ __align__(16) __half2 g_aggh[(size_t)N_PAD * 64];      // agg in fp16
__device__ __align__(16) __half2 g_Wh[CH * CH / 2];               // W in fp16

// ---------------- kernel 1: convert x,W to fp16 + count in-degree -------------
// relies on g_cnt == 0 (.bss on run 1; re-zeroed by k_gemm each run).
__global__ void k_prep_count(const float2* __restrict__ x2,
                             const float2* __restrict__ W2,
                             const int* __restrict__ ei, int E, int n) {
    int i = blockIdx.x * blockDim.x + threadIdx.x;
    int conv = n * 64;
    if (i < conv) g_xh[i] = __float22half2_rn(x2[i]);
    if (i < CH * CH / 2) g_Wh[i] = __float22half2_rn(W2[i]);
    if (i < E) {
        unsigned dst = (unsigned)ei[E + i];
        if (dst < (unsigned)n) atomicAdd(&g_cnt[dst], 1);
    }
    if (i == 0) g_total = 0;
}

// ---------------- kernel 2: allocate CSR ranges (warp-aggregated atomic) ------
__global__ void k_alloc(int n) {
    int i    = blockIdx.x * blockDim.x + threadIdx.x;
    int lane = threadIdx.x & 31;
    int c = (i < n) ? g_cnt[i] : 0;

    int pre = c;
    #pragma unroll
    for (int off = 1; off < 32; off <<= 1) {
        int t = __shfl_up_sync(0xffffffffu, pre, off);
        if (lane >= off) pre += t;
    }
    int base = 0;
    if (lane == 31) base = atomicAdd(&g_total, pre);
    base = __shfl_sync(0xffffffffu, base, 31);
    if (i < n) {
        int rs = base + pre - c;
        g_rowstart[i] = rs;
        g_cursor[i]   = rs;
        g_dinv[i]     = rsqrtf(1.0f + (float)c);   // +1 self loop
    }
}

// ---------------- kernel 3: CSR fill (cursor ends at rowstart+deg) -------------
__global__ void k_fill(const int* __restrict__ ei, int E, int n) {
    int e = blockIdx.x * blockDim.x + threadIdx.x;
    if (e < E) {
        unsigned src = (unsigned)ei[e];
        unsigned dst = (unsigned)ei[E + e];
        if (src < (unsigned)n && dst < (unsigned)n) {
            int pos = atomicAdd(&g_cursor[dst], 1);
            if ((unsigned)pos < (unsigned)E_MAX)
                g_csr_src[pos] = (int)src;
        }
    }
}

// ---------------- kernel 4: gather-aggregate (warp per node, high occupancy) --
__global__ void __launch_bounds__(256)
k_aggregate(int n) {
    int node = (blockIdx.x * blockDim.x + threadIdx.x) >> 5;
    int lane = threadIdx.x & 31;
    if (node >= n) return;

    float di = g_dinv[node];
    uint2 sv = ((const uint2*)(g_xh + (size_t)node * 64))[lane];
    float2 f0 = __half22float2(*(__half2*)&sv.x);
    float2 f1 = __half22float2(*(__half2*)&sv.y);
    float ws = di * di;
    float4 acc = make_float4(f0.x * ws, f0.y * ws, f1.x * ws, f1.y * ws);

    int start = g_rowstart[node];
    int end   = g_cursor[node];          // == rowstart + deg after fill
    int p0 = start;

    // full 32-edge groups: no per-edge bounds checks, unrolled
    for (; p0 + 32 <= end; p0 += 32) {
        int   s = g_csr_src[p0 + lane];
        float w = di * g_dinv[s];
        #pragma unroll 4
        for (int j = 0; j < 32; j++) {
            int   sj = __shfl_sync(0xffffffffu, s, j);
            float wj = __shfl_sync(0xffffffffu, w, j);
            uint2 v  = ((const uint2*)(g_xh + (size_t)sj * 64))[lane];
            float2 a = __half22float2(*(__half2*)&v.x);
            float2 b = __half22float2(*(__half2*)&v.y);
            acc.x += wj * a.x; acc.y += wj * a.y;
            acc.z += wj * b.x; acc.w += wj * b.y;
        }
    }
    // remainder
    if (p0 < end) {
        int myp = p0 + lane;
        int s = 0; float w = 0.0f;
        if (myp < end) {
            s = g_csr_src[myp];
            w = di * g_dinv[s];
        }
        int cnt = end - p0;
        for (int j = 0; j < cnt; j++) {
            int   sj = __shfl_sync(0xffffffffu, s, j);
            float wj = __shfl_sync(0xffffffffu, w, j);
            uint2 v  = ((const uint2*)(g_xh + (size_t)sj * 64))[lane];
            float2 a = __half22float2(*(__half2*)&v.x);
            float2 b = __half22float2(*(__half2*)&v.y);
            acc.x += wj * a.x; acc.y += wj * a.y;
            acc.z += wj * b.x; acc.w += wj * b.y;
        }
    }

    __half2 o0 = __floats2half2_rn(acc.x, acc.y);
    __half2 o1 = __floats2half2_rn(acc.z, acc.w);
    uint2 ov = make_uint2(*(unsigned*)&o0, *(unsigned*)&o1);
    ((uint2*)(g_aggh + (size_t)node * 64))[lane] = ov;
}

// ---------------- kernel 5: HMMA GEMM  out = agg_h @ W_h + bias ---------------
__global__ void __launch_bounds__(256)
k_gemm(const float* __restrict__ bias, float* __restrict__ C, int M) {
    __shared__ __align__(16) __half As[128 * 136];
    __shared__ float Es[8 * 256];

    const int tid  = threadIdx.x;
    const int wid  = tid >> 5;
    const int lane = tid & 31;
    const int row0 = blockIdx.x * 128;
    const int warp_m = wid & 1;
    const int warp_n = wid >> 1;

    {
        const uint4* Ag  = (const uint4*)(g_aggh + (size_t)row0 * 64);
        uint4*       As4 = (uint4*)As;
        #pragma unroll
        for (int i = 0; i < 8; i++) {
            int idx = i * 256 + tid;
            int r   = idx >> 4;
            int c   = idx & 15;
            As4[r * 17 + c] = Ag[idx];
        }
    }
    __syncthreads();

    wmma::fragment<wmma::accumulator, 16, 16, 16, float> acc[4][2];
    #pragma unroll
    for (int mf = 0; mf < 4; mf++)
        #pragma unroll
        for (int nf = 0; nf < 2; nf++)
            wmma::fill_fragment(acc[mf][nf], 0.0f);

    const __half* Wh = (const __half*)g_Wh;

    #pragma unroll
    for (int k0 = 0; k0 < 128; k0 += 16) {
        wmma::fragment<wmma::matrix_a, 16, 16, 16, __half, wmma::row_major> af[4];
        #pragma unroll
        for (int mf = 0; mf < 4; mf++)
            wmma::load_matrix_sync(af[mf],
                As + (warp_m * 64 + mf * 16) * 136 + k0, 136);
        #pragma unroll
        for (int nf = 0; nf < 2; nf++) {
            wmma::fragment<wmma::matrix_b, 16, 16, 16, __half, wmma::row_major> bf;
            wmma::load_matrix_sync(bf, Wh + k0 * CH + warp_n * 32 + nf * 16, CH);
            #pragma unroll
            for (int mf = 0; mf < 4; mf++)
                wmma::mma_sync(acc[mf][nf], af[mf], bf, acc[mf][nf]);
        }
    }

    float* es = Es + wid * 256;
    #pragma unroll
    for (int mf = 0; mf < 4; mf++) {
        #pragma unroll
        for (int nf = 0; nf < 2; nf++) {
            wmma::store_matrix_sync(es, acc[mf][nf], 16, wmma::mem_row_major);
            __syncwarp();
            int r_in = lane >> 1;
            int c0   = (lane & 1) * 8;
            int gr   = row0 + warp_m * 64 + mf * 16 + r_in;
            int gc   = warp_n * 32 + nf * 16 + c0;
            if (gr < M) {
                float4 b0 = *(const float4*)(bias + gc);
                float4 b1 = *(const float4*)(bias + gc + 4);
                const float* p = es + r_in * 16 + c0;
                float4 o0 = make_float4(p[0] + b0.x, p[1] + b0.y,
                                        p[2] + b0.z, p[3] + b0.w);
                float4 o1 = make_float4(p[4] + b1.x, p[5] + b1.y,
                                        p[6] + b1.z, p[7] + b1.w);
                *(float4*)(C + (size_t)gr * CH + gc)     = o0;
                *(float4*)(C + (size_t)gr * CH + gc + 4) = o1;
            }
            __syncwarp();
        }
    }

    // restore invariant: g_cnt == 0 for next graph replay
    int gz = blockIdx.x * 256 + tid;
    if (gz < M) g_cnt[gz] = 0;
}

// ---------------- launch --------------------------------------------------------
extern "C" void kernel_launch(void* const* d_in, const int* in_sizes, int n_in,
                              void* d_out, int out_size) {
    const float* x    = (const float*)d_in[0];
    const int*   ei   = (const int*)d_in[1];     // int32 [2, E]
    const float* W    = (const float*)d_in[2];
    const float* bias = (const float*)d_in[3];
    float*       out  = (float*)d_out;

    int N = in_sizes[0] / CH;   // 100000
    int E = in_sizes[1] / 2;    // 1600000

    int prep_threads = N * 64;
    if (prep_threads < E) prep_threads = E;

    k_prep_count<<<(prep_threads + 255) / 256, 256>>>((const float2*)x,
                                                      (const float2*)W, ei, E, N);
    k_alloc     <<<(N + 255) / 256, 256>>>(N);
    k_fill      <<<(E + 255) / 256, 256>>>(ei, E, N);
    k_aggregate <<<(N * 32 + 255) / 256, 256>>>(N);
    k_gemm      <<<(N + 127) / 128, 256>>>(bias, out, N);
}